// round 17
// baseline (speedup 1.0000x reference)
#include <cuda_runtime.h>

// QuantumLayer, 2-kernel split + PDL; ELEMENT-PACKED eval (lane0=elem0,
// lane1=elem1) so features cost half the registers:
//  z_w(x) = sum_{u,v} C[w][u][v]*p01[u]*p23[v], features (1, cos x, sin x).
// C is staged lane-duplicated in shared (81 x 4 f32x2). True eval live set
// ~60 regs under the 73-reg cap (7 blocks/SM, grid=1024 single wave) ->
// first genuinely spill-free EPT=2 contraction.

#define TPB 128
#define EPT 2

typedef unsigned long long ull;

__device__ float4 g_C[81];   // [u*9+v] -> (C_w0, C_w1, C_w2, C_w3)

__device__ __forceinline__ ull pk2(float lo, float hi) {
    ull r; asm("mov.b64 %0,{%1,%2};" : "=l"(r) : "f"(lo), "f"(hi)); return r;
}
__device__ __forceinline__ void upk2(ull a, float& lo, float& hi) {
    asm("mov.b64 {%0,%1},%2;" : "=f"(lo), "=f"(hi) : "l"(a));
}
__device__ __forceinline__ ull fma2(ull a, ull b, ull c) {
    ull d; asm("fma.rn.f32x2 %0,%1,%2,%3;" : "=l"(d) : "l"(a), "l"(b), "l"(c)); return d;
}
__device__ __forceinline__ ull mul2(ull a, ull b) {
    ull d; asm("mul.rn.f32x2 %0,%1,%2;" : "=l"(d) : "l"(a), "l"(b)); return d;
}

// ---------------------------------------------------------------------------
// Kernel 1: shuffle-parallel build of C. Thread tid = j*16 + i owns U[i][j].
// ---------------------------------------------------------------------------
__global__ void build_coeff_kernel(const float* __restrict__ weights) {
    cudaTriggerProgrammaticLaunchCompletion();   // let eval's prologue start now
    __shared__ float sUr[16][16], sUi[16][16];
    __shared__ float sM[256 * 4];                // [(j*16+k)*4 + w]
    const int tid = threadIdx.x;
    const int i = tid & 15;

    float vr = (i == (tid >> 4)) ? 1.0f : 0.0f;
    float vi = 0.0f;
#pragma unroll
    for (int l = 0; l < 5; ++l) {
#pragma unroll
        for (int w = 0; w < 4; ++w) {
            const float phi   = __ldg(&weights[(l * 4 + w) * 3 + 0]);
            const float theta = __ldg(&weights[(l * 4 + w) * 3 + 1]);
            const float omega = __ldg(&weights[(l * 4 + w) * 3 + 2]);
            float sp, cp, sm, cm, st, ct;
            __sincosf(0.5f * (phi + omega), &sp, &cp);
            __sincosf(0.5f * (phi - omega), &sm, &cm);
            __sincosf(0.5f * theta, &st, &ct);
            const int m = 8 >> w;
            const float pr = __shfl_xor_sync(0xffffffffu, vr, m);
            const float pi = __shfl_xor_sync(0xffffffffu, vi, m);
            const bool bit = (i & m) != 0;
            const float cAr = cp * ct;
            const float cAi = bit ? sp * ct : -sp * ct;
            const float cBr = bit ? cm * st : -cm * st;
            const float cBi = -sm * st;
            const float nvr = cAr * vr - cAi * vi + cBr * pr - cBi * pi;
            const float nvi = cAr * vi + cAi * vr + cBr * pi + cBi * pr;
            vr = nvr; vi = nvi;
        }
        const int r = (l % 3) + 1;
#pragma unroll
        for (int w = 0; w < 4; ++w) {
            const int mc = 8 >> w;
            const int mt = 8 >> ((w + r) & 3);
            const float pr = __shfl_xor_sync(0xffffffffu, vr, mt);
            const float pi = __shfl_xor_sync(0xffffffffu, vi, mt);
            if (i & mc) { vr = pr; vi = pi; }
        }
    }
    sUr[i][tid >> 4] = vr;
    sUi[i][tid >> 4] = vi;
    __syncthreads();

    {   // M_w[j][k] = sum_i sign_w(i) Re(conj U_ij * U_ik)
        const int j = tid >> 4, k = tid & 15;
        float m0 = 0.f, m1 = 0.f, m2 = 0.f, m3 = 0.f;
#pragma unroll
        for (int ii = 0; ii < 16; ++ii) {
            const float p = sUr[ii][j] * sUr[ii][k] + sUi[ii][j] * sUi[ii][k];
            m0 += (ii & 8) ? -p : p;
            m1 += (ii & 4) ? -p : p;
            m2 += (ii & 2) ? -p : p;
            m3 += (ii & 1) ? -p : p;
        }
        sM[tid * 4 + 0] = m0; sM[tid * 4 + 1] = m1;
        sM[tid * 4 + 2] = m2; sM[tid * 4 + 3] = m3;
    }
    __syncthreads();

    if (tid < 81) {  // project M_w onto (1, cos, sin)^{x4} basis
        const int t0 = tid / 27, t1 = (tid / 9) % 3, t2 = (tid / 3) % 3, t3 = tid % 3;
        const int tt[4] = {t0, t1, t2, t3};
        float a0 = 0.f, a1 = 0.f, a2 = 0.f, a3 = 0.f;
#pragma unroll
        for (int b = 0; b < 16; ++b) {
            int j = 0, k = 0; float sgn = 1.0f;
#pragma unroll
            for (int q = 0; q < 4; ++q) {
                const int o = (b >> q) & 1;
                const int ti = tt[q];
                int jq, kq;
                if (ti == 2) { jq = o; kq = 1 - o; }
                else { jq = o; kq = o; if (ti == 1 && o) sgn = -sgn; }
                j = (j << 1) | jq;
                k = (k << 1) | kq;
            }
            const float* m = &sM[(j * 16 + k) * 4];
            a0 += sgn * m[0]; a1 += sgn * m[1];
            a2 += sgn * m[2]; a3 += sgn * m[3];
        }
        const int u = t0 * 3 + t1, v = t2 * 3 + t3;
        g_C[u * 9 + v] = make_float4(a0 * 0.0625f, a1 * 0.0625f,
                                     a2 * 0.0625f, a3 * 0.0625f);
    }
}

// ---------------------------------------------------------------------------
// Kernel 2 (PDL secondary): element-packed contraction, 2 elements/thread.
// ---------------------------------------------------------------------------
__global__ __launch_bounds__(TPB, 7)
void qforward_kernel(const float4* __restrict__ x, float4* __restrict__ out, int B) {
    __shared__ __align__(16) ull shC[81 * 4];    // [uv*4 + w], lanes duplicated

    const int i0 = blockIdx.x * (TPB * EPT) + threadIdx.x;
    const int i1 = i0 + TPB;

    // ---------- prologue: independent of C, overlaps the builder ----------
    const float4 xa = (i0 < B) ? x[i0] : make_float4(0.f, 0.f, 0.f, 0.f);
    const float4 xb = (i1 < B) ? x[i1] : make_float4(0.f, 0.f, 0.f, 0.f);
    const ull ONE = pk2(1.0f, 1.0f);

    // element-packed feature factors (lane0 = elem0, lane1 = elem1)
    float c0a, s0a, c1a, s1a, c2a, s2a, c3a, s3a;
    float c0b, s0b, c1b, s1b, c2b, s2b, c3b, s3b;
    __sincosf(xa.x, &s0a, &c0a); __sincosf(xa.y, &s1a, &c1a);
    __sincosf(xa.z, &s2a, &c2a); __sincosf(xa.w, &s3a, &c3a);
    __sincosf(xb.x, &s0b, &c0b); __sincosf(xb.y, &s1b, &c1b);
    __sincosf(xb.z, &s2b, &c2b); __sincosf(xb.w, &s3b, &c3b);

    const ull c2p = pk2(c2a, c2b), s2p = pk2(s2a, s2b);
    const ull c3p = pk2(c3a, c3b), s3p = pk2(s3a, s3b);
    ull p23p[9];
    p23p[0] = ONE; p23p[1] = c3p; p23p[2] = s3p;
    p23p[3] = c2p; p23p[4] = mul2(c2p, c3p); p23p[5] = mul2(c2p, s3p);
    p23p[6] = s2p; p23p[7] = mul2(s2p, c3p); p23p[8] = mul2(s2p, s3p);

    ull F0[3], F1[3];
    F0[0] = ONE; F0[1] = pk2(c0a, c0b); F0[2] = pk2(s0a, s0b);
    F1[0] = ONE; F1[1] = pk2(c1a, c1b); F1[2] = pk2(s1a, s1b);

    // ---------- wait for builder's g_C, stage lane-duplicated to shared -----
    cudaGridDependencySynchronize();
    if (threadIdx.x < 81) {
        const float4 c = g_C[threadIdx.x];
        shC[4 * threadIdx.x + 0] = pk2(c.x, c.x);
        shC[4 * threadIdx.x + 1] = pk2(c.y, c.y);
        shC[4 * threadIdx.x + 2] = pk2(c.z, c.z);
        shC[4 * threadIdx.x + 3] = pk2(c.w, c.w);
    }
    __syncthreads();

    // ---------- contraction: z_w = sum_u p01[u] * (sum_v C_w[u][v]*p23[v]) --
    const ulonglong2* __restrict__ C4 = reinterpret_cast<const ulonglong2*>(shC);
    ull z0, z1, z2, z3;
    {   // u = 0 (p01 factor = 1): accumulate straight into z
        ull a0 = 0ull, a1 = 0ull, a2 = 0ull, a3 = 0ull;
#pragma unroll
        for (int v = 0; v < 9; ++v) {
            const ulonglong2 cA = C4[v * 2 + 0];  // (w0, w1), lanes duplicated
            const ulonglong2 cB = C4[v * 2 + 1];  // (w2, w3)
            a0 = fma2(cA.x, p23p[v], a0);
            a1 = fma2(cA.y, p23p[v], a1);
            a2 = fma2(cB.x, p23p[v], a2);
            a3 = fma2(cB.y, p23p[v], a3);
        }
        z0 = a0; z1 = a1; z2 = a2; z3 = a3;
    }
#pragma unroll
    for (int u = 1; u < 9; ++u) {
        ull a0 = 0ull, a1 = 0ull, a2 = 0ull, a3 = 0ull;
#pragma unroll
        for (int v = 0; v < 9; ++v) {
            const ulonglong2 cA = C4[(u * 9 + v) * 2 + 0];
            const ulonglong2 cB = C4[(u * 9 + v) * 2 + 1];
            a0 = fma2(cA.x, p23p[v], a0);
            a1 = fma2(cA.y, p23p[v], a1);
            a2 = fma2(cB.x, p23p[v], a2);
            a3 = fma2(cB.y, p23p[v], a3);
        }
        const int ua = u / 3, ub = u % 3;        // compile-time per unrolled u
        ull pu;
        if (ua == 0)      pu = F1[ub];
        else if (ub == 0) pu = F0[ua];
        else              pu = mul2(F0[ua], F1[ub]);
        z0 = fma2(a0, pu, z0);
        z1 = fma2(a1, pu, z1);
        z2 = fma2(a2, pu, z2);
        z3 = fma2(a3, pu, z3);
    }

    // ---------- unpack element lanes, store ----------
    float w0a, w0b, w1a, w1b, w2a, w2b, w3a, w3b;
    upk2(z0, w0a, w0b); upk2(z1, w1a, w1b);
    upk2(z2, w2a, w2b); upk2(z3, w3a, w3b);
    if (i0 < B) out[i0] = make_float4(w0a, w1a, w2a, w3a);
    if (i1 < B) out[i1] = make_float4(w0b, w1b, w2b, w3b);
}

// ---------------------------------------------------------------------------
extern "C" void kernel_launch(void* const* d_in, const int* in_sizes, int n_in,
                              void* d_out, int out_size) {
    int bx = 0, bw = 1;
    if (n_in >= 2 && in_sizes[0] == 60) { bx = 1; bw = 0; }
    const float* x   = (const float*)d_in[bx];
    const float* wts = (const float*)d_in[bw];
    const int B = in_sizes[bx] / 4;

    build_coeff_kernel<<<1, 256>>>(wts);

    const int grid = (B + TPB * EPT - 1) / (TPB * EPT);
    cudaLaunchConfig_t cfg = {};
    cfg.gridDim  = dim3((unsigned)grid, 1, 1);
    cfg.blockDim = dim3(TPB, 1, 1);
    cudaLaunchAttribute attrs[1];
    attrs[0].id = cudaLaunchAttributeProgrammaticStreamSerialization;
    attrs[0].val.programmaticStreamSerializationAllowed = 1;
    cfg.attrs = attrs;
    cfg.numAttrs = 1;
    cudaLaunchKernelEx(&cfg, qforward_kernel, (const float4*)x, (float4*)d_out, B);
}